// round 13
// baseline (speedup 1.0000x reference)
#include <cuda_runtime.h>

#define VOCAB 32000
#define BATCH 4
#define SEQ   2048
#define NVEC  (VOCAB / 4)   // 8000 float4 per row
#define NOUT4 ((BATCH * VOCAB) / 4)   // 32000 float4 of output
#define TOTAL (BATCH * SEQ)           // 8192 rows

// Scratch state. Zero-initialized at module load; the scatter kernel restores
// everything it dirtied to zero, so every launch (correctness run and every
// graph replay) sees identical initial state.
__device__ int g_hist[BATCH * VOCAB];
__device__ int g_list[TOTAL];     // distinct touched buckets (<= 8192)
__device__ int g_listn = 0;       // touched-bucket count

// One CTA per (b, s) row. Also writes this CTA's 4-float4 slice of zeros to
// `out` (zeros are the correct value for every untouched bucket and for the
// special tokens; touched buckets are overwritten by the scatter kernel).
__global__ __launch_bounds__(256, 8)
void argmax_hist_kernel(const float* __restrict__ logits,
                        float* __restrict__ out) {
    const int row = blockIdx.x;                       // 0 .. B*S-1
    const float4* __restrict__ p =
        reinterpret_cast<const float4*>(logits + (size_t)row * VOCAB);
    const int tid = threadIdx.x;

    // Baseline zeros: 8192 CTAs x 4 float4 covers all 32000*4 outputs... 
    // (TOTAL*4 = 32768 >= NOUT4 = 32000, so guard the tail).
    if (tid < 4) {
        const int oi = (row << 2) + tid;
        if (oi < NOUT4)
            reinterpret_cast<float4*>(out)[oi] = make_float4(0.f, 0.f, 0.f, 0.f);
    }

    float best = -3.402823466e+38f;
    int   bidx = 0;

    // Strided float4 scan, streaming (evict-first) loads. Strict '>' keeps
    // the first (lowest-index) max within a thread, matching jnp.argmax.
    #pragma unroll 4
    for (int i = tid; i < NVEC; i += 256) {
        float4 v = __ldcs(p + i);
        int base = i << 2;
        if (v.x > best) { best = v.x; bidx = base;     }
        if (v.y > best) { best = v.y; bidx = base + 1; }
        if (v.z > best) { best = v.z; bidx = base + 2; }
        if (v.w > best) { best = v.w; bidx = base + 3; }
    }

    // Warp reduction (tie -> smaller index)
    #pragma unroll
    for (int off = 16; off > 0; off >>= 1) {
        float ov = __shfl_down_sync(0xFFFFFFFFu, best, off);
        int   oi = __shfl_down_sync(0xFFFFFFFFu, bidx, off);
        if (ov > best || (ov == best && oi < bidx)) { best = ov; bidx = oi; }
    }

    __shared__ float s_val[8];
    __shared__ int   s_idx[8];
    const int wid = tid >> 5;
    const int lid = tid & 31;
    if (lid == 0) { s_val[wid] = best; s_idx[wid] = bidx; }
    __syncthreads();

    if (wid == 0) {
        best = (lid < 8) ? s_val[lid] : -3.402823466e+38f;
        bidx = (lid < 8) ? s_idx[lid] : 0x7FFFFFFF;
        #pragma unroll
        for (int off = 4; off > 0; off >>= 1) {
            float ov = __shfl_down_sync(0xFFFFFFFFu, best, off);
            int   oi = __shfl_down_sync(0xFFFFFFFFu, bidx, off);
            if (ov > best || (ov == best && oi < bidx)) { best = ov; bidx = oi; }
        }
        if (lid == 0) {
            const int bucket = (row / SEQ) * VOCAB + bidx;
            int old = atomicAdd(&g_hist[bucket], 1);
            if (old == 0) {                      // first toucher lists it
                int pos = atomicAdd(&g_listn, 1);
                g_list[pos] = bucket;
            }
        }
    }
}

// Single-CTA scatter: process only the touched buckets (<= 8192). Writes the
// final value for non-special buckets, resets the dirtied hist entries and
// the list counter for the next replay.
__global__ __launch_bounds__(1024)
void scatter_kernel(float* __restrict__ out) {
    const int n = g_listn;
    for (int i = threadIdx.x; i < n; i += 1024) {
        const int bucket = g_list[i];
        const int c = g_hist[bucket];
        g_hist[bucket] = 0;                      // reset for next replay
        const int v = bucket % VOCAB;
        if (v > 2)                               // PAD=0, START=1, END=2 stay 0
            out[bucket] = fminf((float)c, 4.0f) * 0.25f;
    }
    __syncthreads();                             // all reads of g_listn done
    if (threadIdx.x == 0) g_listn = 0;           // reset for next replay
}

extern "C" void kernel_launch(void* const* d_in, const int* in_sizes, int n_in,
                              void* d_out, int out_size) {
    const float* logits = (const float*)d_in[0];
    float* out = (float*)d_out;

    argmax_hist_kernel<<<TOTAL, 256>>>(logits, out);
    scatter_kernel<<<1, 1024>>>(out);
}

// round 15
// speedup vs baseline: 1.0835x; 1.0835x over previous
#include <cuda_runtime.h>

#define VOCAB 32000
#define BATCH 4
#define SEQ   2048
#define NVEC  (VOCAB / 4)   // 8000 float4 per row
#define NOUT4 ((BATCH * VOCAB) / 4)   // 32000 float4 of output
#define TOTAL (BATCH * SEQ)           // 8192 rows
#define SCTA  64                      // scatter CTAs
#define STHR  128                     // scatter threads per CTA

// Scratch state. Zero-initialized at module load; the scatter kernel restores
// everything it dirtied to zero, so every launch (correctness run and every
// graph replay) sees identical initial state.
__device__ int g_hist[BATCH * VOCAB];
__device__ int g_list[TOTAL];     // distinct touched buckets (<= 8192)
__device__ int g_listn = 0;       // touched-bucket count
__device__ unsigned g_sfin = 0;   // scatter CTAs finished (for reset ticket)

// One CTA per (b, s) row. Also writes this CTA's 4-float4 slice of zeros to
// `out` (zeros are correct for every untouched bucket and special tokens;
// touched buckets are overwritten by the scatter kernel).
__global__ __launch_bounds__(256, 8)
void argmax_hist_kernel(const float* __restrict__ logits,
                        float* __restrict__ out) {
    const int row = blockIdx.x;                       // 0 .. B*S-1
    const float4* __restrict__ p =
        reinterpret_cast<const float4*>(logits + (size_t)row * VOCAB);
    const int tid = threadIdx.x;

    // Baseline zeros: 8192 CTAs x 4 float4 covers all outputs (guard tail).
    if (tid < 4) {
        const int oi = (row << 2) + tid;
        if (oi < NOUT4)
            reinterpret_cast<float4*>(out)[oi] = make_float4(0.f, 0.f, 0.f, 0.f);
    }

    float best = -3.402823466e+38f;
    int   bidx = 0;

    // Strided float4 scan, streaming (evict-first) loads. Strict '>' keeps
    // the first (lowest-index) max within a thread, matching jnp.argmax.
    #pragma unroll 4
    for (int i = tid; i < NVEC; i += 256) {
        float4 v = __ldcs(p + i);
        int base = i << 2;
        if (v.x > best) { best = v.x; bidx = base;     }
        if (v.y > best) { best = v.y; bidx = base + 1; }
        if (v.z > best) { best = v.z; bidx = base + 2; }
        if (v.w > best) { best = v.w; bidx = base + 3; }
    }

    // Warp reduction (tie -> smaller index)
    #pragma unroll
    for (int off = 16; off > 0; off >>= 1) {
        float ov = __shfl_down_sync(0xFFFFFFFFu, best, off);
        int   oi = __shfl_down_sync(0xFFFFFFFFu, bidx, off);
        if (ov > best || (ov == best && oi < bidx)) { best = ov; bidx = oi; }
    }

    __shared__ float s_val[8];
    __shared__ int   s_idx[8];
    const int wid = tid >> 5;
    const int lid = tid & 31;
    if (lid == 0) { s_val[wid] = best; s_idx[wid] = bidx; }
    __syncthreads();

    if (wid == 0) {
        best = (lid < 8) ? s_val[lid] : -3.402823466e+38f;
        bidx = (lid < 8) ? s_idx[lid] : 0x7FFFFFFF;
        #pragma unroll
        for (int off = 4; off > 0; off >>= 1) {
            float ov = __shfl_down_sync(0xFFFFFFFFu, best, off);
            int   oi = __shfl_down_sync(0xFFFFFFFFu, bidx, off);
            if (ov > best || (ov == best && oi < bidx)) { best = ov; bidx = oi; }
        }
        if (lid == 0) {
            const int bucket = (row / SEQ) * VOCAB + bidx;
            int old = atomicAdd(&g_hist[bucket], 1);
            if (old == 0) {                      // first toucher lists it
                int pos = atomicAdd(&g_listn, 1);
                g_list[pos] = bucket;
            }
        }
    }
}

// Multi-CTA scatter: 64 CTAs x 128 threads = 8192 threads, one touched
// bucket per thread (all scattered loads in flight chip-wide). Writes final
// values, resets dirtied hist entries; the last CTA to finish resets the
// list counter (every CTA read g_listn before its g_sfin increment, so the
// reset cannot race a reader).
__global__ __launch_bounds__(STHR)
void scatter_kernel(float* __restrict__ out) {
    const int n = g_listn;
    const int i = blockIdx.x * STHR + threadIdx.x;
    if (i < n) {
        const int bucket = g_list[i];
        const int c = g_hist[bucket];
        g_hist[bucket] = 0;                      // reset for next replay
        const int v = bucket % VOCAB;
        if (v > 2)                               // PAD=0, START=1, END=2 stay 0
            out[bucket] = fminf((float)c, 4.0f) * 0.25f;
    }
    __syncthreads();
    if (threadIdx.x == 0) {
        __threadfence();
        unsigned f = atomicAdd(&g_sfin, 1u);
        if (f == SCTA - 1) {                     // last finisher resets counters
            g_listn = 0;
            atomicExch(&g_sfin, 0u);
        }
    }
}

extern "C" void kernel_launch(void* const* d_in, const int* in_sizes, int n_in,
                              void* d_out, int out_size) {
    const float* logits = (const float*)d_in[0];
    float* out = (float*)d_out;

    argmax_hist_kernel<<<TOTAL, 256>>>(logits, out);
    scatter_kernel<<<SCTA, STHR>>>(out);
}

// round 16
// speedup vs baseline: 1.1069x; 1.0215x over previous
#include <cuda_runtime.h>

#define VOCAB 32000
#define BATCH 4
#define SEQ   2048
#define NVEC  (VOCAB / 4)   // 8000 float4 per row
#define NOUT4 ((BATCH * VOCAB) / 4)   // 32000 float4 of output
#define TOTAL (BATCH * SEQ)           // 8192 rows
#define SCTA  64                      // scatter CTAs
#define STHR  128                     // scatter threads per CTA (64*128 = TOTAL)

// Scratch state. g_hist is zero at module load; the scatter kernel resets
// every dirtied entry (idempotent duplicate stores), so every launch sees a
// zero histogram. g_list needs no init/reset: argmax overwrites all TOTAL
// entries before scatter reads them.
__device__ int g_hist[BATCH * VOCAB];
__device__ int g_list[TOTAL];     // per-row winning bucket (duplicates OK)

// One CTA per (b, s) row. Writes this CTA's 4-float4 slice of zeros to `out`
// (zeros are correct for untouched buckets and special tokens; touched
// buckets are overwritten by the scatter kernel), then argmax + hist add +
// plain store of the bucket into g_list[row].
__global__ __launch_bounds__(256, 8)
void argmax_hist_kernel(const float* __restrict__ logits,
                        float* __restrict__ out) {
    const int row = blockIdx.x;                       // 0 .. B*S-1
    const float4* __restrict__ p =
        reinterpret_cast<const float4*>(logits + (size_t)row * VOCAB);
    const int tid = threadIdx.x;

    // Baseline zeros: 8192 CTAs x 4 float4 covers all outputs (guard tail).
    if (tid < 4) {
        const int oi = (row << 2) + tid;
        if (oi < NOUT4)
            reinterpret_cast<float4*>(out)[oi] = make_float4(0.f, 0.f, 0.f, 0.f);
    }

    float best = -3.402823466e+38f;
    int   bidx = 0;

    // Strided float4 scan, streaming (evict-first) loads. Strict '>' keeps
    // the first (lowest-index) max within a thread, matching jnp.argmax.
    #pragma unroll 4
    for (int i = tid; i < NVEC; i += 256) {
        float4 v = __ldcs(p + i);
        int base = i << 2;
        if (v.x > best) { best = v.x; bidx = base;     }
        if (v.y > best) { best = v.y; bidx = base + 1; }
        if (v.z > best) { best = v.z; bidx = base + 2; }
        if (v.w > best) { best = v.w; bidx = base + 3; }
    }

    // Warp reduction (tie -> smaller index)
    #pragma unroll
    for (int off = 16; off > 0; off >>= 1) {
        float ov = __shfl_down_sync(0xFFFFFFFFu, best, off);
        int   oi = __shfl_down_sync(0xFFFFFFFFu, bidx, off);
        if (ov > best || (ov == best && oi < bidx)) { best = ov; bidx = oi; }
    }

    __shared__ float s_val[8];
    __shared__ int   s_idx[8];
    const int wid = tid >> 5;
    const int lid = tid & 31;
    if (lid == 0) { s_val[wid] = best; s_idx[wid] = bidx; }
    __syncthreads();

    if (wid == 0) {
        best = (lid < 8) ? s_val[lid] : -3.402823466e+38f;
        bidx = (lid < 8) ? s_idx[lid] : 0x7FFFFFFF;
        #pragma unroll
        for (int off = 4; off > 0; off >>= 1) {
            float ov = __shfl_down_sync(0xFFFFFFFFu, best, off);
            int   oi = __shfl_down_sync(0xFFFFFFFFu, bidx, off);
            if (ov > best || (ov == best && oi < bidx)) { best = ov; bidx = oi; }
        }
        if (lid == 0) {
            const int bucket = (row / SEQ) * VOCAB + bidx;
            atomicAdd(&g_hist[bucket], 1);
            g_list[row] = bucket;            // plain store, no counter
        }
    }
}

// Scatter: exactly TOTAL threads, one list entry each. Duplicate entries all
// read the SAME final count (this kernel runs after argmax completes) and
// write identical values -> idempotent, deterministic. Chain is just
// list-load -> hist-load. No counters, no atomics, no fences.
__global__ __launch_bounds__(STHR)
void scatter_kernel(float* __restrict__ out) {
    const int i = blockIdx.x * STHR + threadIdx.x;    // 0 .. TOTAL-1
    const int bucket = g_list[i];
    const int c = g_hist[bucket];
    const int v = bucket % VOCAB;
    if (c != 0) {                        // skip already-reset duplicates' work
        g_hist[bucket] = 0;              // idempotent reset for next replay
        if (v > 2)                       // PAD=0, START=1, END=2 stay 0
            out[bucket] = fminf((float)c, 4.0f) * 0.25f;
    } else if (v > 2) {
        // c==0 means another duplicate thread (same launch) already reset it;
        // recompute nothing — its write carries the identical final value.
        // (No action needed: out[bucket] is written by the thread that saw c.)
    }
}

extern "C" void kernel_launch(void* const* d_in, const int* in_sizes, int n_in,
                              void* d_out, int out_size) {
    const float* logits = (const float*)d_in[0];
    float* out = (float*)d_out;

    argmax_hist_kernel<<<TOTAL, 256>>>(logits, out);
    scatter_kernel<<<SCTA, STHR>>>(out);
}